// round 1
// baseline (speedup 1.0000x reference)
#include <cuda_runtime.h>

// Problem constants (B, N, T, H) = (16, 256, 96, 128)
#define BB 16
#define NN 256
#define TT 96
#define HH 128
#define EPS 1e-5f

// Scratch for C[t,k] = time_emb @ W3  (96 x 128 floats = 48 KB, stays in L2)
__device__ float g_C[TT * HH];

// ---------------------------------------------------------------------------
// Tiny kernel: C[t,k] = sum_h time_emb[t,h] * Wf[(2H+h)*H + k]
// Grid: TT blocks x HH threads. ~2.4 MFLOP total.
// ---------------------------------------------------------------------------
__global__ void time_proj_kernel(const float* __restrict__ time_emb,
                                 const float* __restrict__ Wf) {
    const int t = blockIdx.x;
    const int k = threadIdx.x;
    const float* __restrict__ W3 = Wf + 2 * HH * HH;
    const float* __restrict__ te = time_emb + t * HH;
    float acc = 0.f;
#pragma unroll 8
    for (int h = 0; h < HH; h++) {
        acc += te[h] * W3[h * HH + k];  // coalesced over k
    }
    g_C[t * HH + k] = acc;
}

// ---------------------------------------------------------------------------
// Main fused kernel. One block per (b, n) pair (4096 blocks, 256 threads).
// Phase 1: threads [0,128) compute proj[h] = bp[h] + sum_t x[b,n,t]*Wp[t,h]
//          threads [128,256) compute node_s[k] = sum_h node_emb[n,h]*W2[h,k]
// Phase 2: threads [0,128) compute A[k] = bf[k] + node_s[k] + sum_h proj[h]*W1[h,k]
// Phase 3: 8 warps stream t = warp, warp+8, ... 96:
//          row = relu(A + C[t]); layernorm over H=128 via warp shfl; float4 store.
// ---------------------------------------------------------------------------
__global__ __launch_bounds__(256) void gpe_main_kernel(
    const float* __restrict__ x,
    const float* __restrict__ Wp,
    const float* __restrict__ bp,
    const float* __restrict__ Wf,
    const float* __restrict__ bf,
    const float* __restrict__ gamma,
    const float* __restrict__ beta,
    const float* __restrict__ node_emb,
    float* __restrict__ out) {

    __shared__ float x_s[TT];
    __shared__ float proj_s[HH];
    __shared__ float node_s[HH];
    __shared__ float A_s[HH];
    __shared__ float g_s[HH];
    __shared__ float b_s[HH];

    const int bid = blockIdx.x;       // b * NN + n
    const int n   = bid & (NN - 1);   // NN = 256, power of 2
    const int tid = threadIdx.x;

    // Stage block-local data
    if (tid < TT) x_s[tid] = x[(size_t)bid * TT + tid];
    if (tid < HH) { g_s[tid] = gamma[tid]; b_s[tid] = beta[tid]; }
    __syncthreads();

    if (tid < HH) {
        // proj[h] = bp[h] + sum_t x[t] * Wp[t,h]   (Wp read coalesced over h)
        float acc = bp[tid];
#pragma unroll 6
        for (int t = 0; t < TT; t++) {
            acc += x_s[t] * Wp[t * HH + tid];
        }
        proj_s[tid] = acc;
    } else {
        // node_s[k] = sum_h node_emb[n,h] * W2[h,k]
        const int k = tid - HH;
        const float* __restrict__ W2 = Wf + HH * HH;
        const float* __restrict__ ne = node_emb + n * HH;
        float acc = 0.f;
#pragma unroll 8
        for (int h = 0; h < HH; h++) {
            acc += ne[h] * W2[h * HH + k];
        }
        node_s[k] = acc;
    }
    __syncthreads();

    if (tid < HH) {
        // A[k] = bf[k] + node_s[k] + sum_h proj[h] * W1[h,k]
        float acc = bf[tid] + node_s[tid];
#pragma unroll 8
        for (int h = 0; h < HH; h++) {
            acc += proj_s[h] * Wf[h * HH + tid];
        }
        A_s[tid] = acc;
    }
    __syncthreads();

    // Phase 3: stream the 96 t-rows, one row per warp per iteration.
    const int warp = tid >> 5;
    const int lane = tid & 31;

    const float4 a  = reinterpret_cast<const float4*>(A_s)[lane];
    const float4 gg = reinterpret_cast<const float4*>(g_s)[lane];
    const float4 bb = reinterpret_cast<const float4*>(b_s)[lane];

    for (int t = warp; t < TT; t += 8) {
        const float4 c = __ldg(reinterpret_cast<const float4*>(g_C + t * HH) + lane);

        float4 v;
        v.x = fmaxf(a.x + c.x, 0.f);
        v.y = fmaxf(a.y + c.y, 0.f);
        v.z = fmaxf(a.z + c.z, 0.f);
        v.w = fmaxf(a.w + c.w, 0.f);

        float s1 = v.x + v.y + v.z + v.w;
        float s2 = v.x * v.x + v.y * v.y + v.z * v.z + v.w * v.w;
#pragma unroll
        for (int off = 16; off > 0; off >>= 1) {
            s1 += __shfl_xor_sync(0xffffffffu, s1, off);
            s2 += __shfl_xor_sync(0xffffffffu, s2, off);
        }
        const float mean = s1 * (1.f / HH);
        const float var  = s2 * (1.f / HH) - mean * mean;
        const float rstd = rsqrtf(var + EPS);

        float4 o4;
        o4.x = (v.x - mean) * rstd * gg.x + bb.x;
        o4.y = (v.y - mean) * rstd * gg.y + bb.y;
        o4.z = (v.z - mean) * rstd * gg.z + bb.z;
        o4.w = (v.w - mean) * rstd * gg.w + bb.w;

        reinterpret_cast<float4*>(out + ((size_t)bid * TT + t) * HH)[lane] = o4;
    }
}

// ---------------------------------------------------------------------------
// kernel_launch — inputs per metadata order:
//  0: x (B,N,T)  1: Wp (T,H)  2: bp (H)  3: Wf (3H,H)  4: bf (H)
//  5: gamma (H)  6: beta (H)  7: node_emb (N,H)  8: time_emb (T,H)
// ---------------------------------------------------------------------------
extern "C" void kernel_launch(void* const* d_in, const int* in_sizes, int n_in,
                              void* d_out, int out_size) {
    const float* x        = (const float*)d_in[0];
    const float* Wp       = (const float*)d_in[1];
    const float* bp       = (const float*)d_in[2];
    const float* Wf       = (const float*)d_in[3];
    const float* bf       = (const float*)d_in[4];
    const float* gamma    = (const float*)d_in[5];
    const float* beta     = (const float*)d_in[6];
    const float* node_emb = (const float*)d_in[7];
    const float* time_emb = (const float*)d_in[8];
    float* out = (float*)d_out;

    time_proj_kernel<<<TT, HH>>>(time_emb, Wf);
    gpe_main_kernel<<<BB * NN, 256>>>(x, Wp, bp, Wf, bf, gamma, beta,
                                      node_emb, out);
}

// round 2
// speedup vs baseline: 1.4964x; 1.4964x over previous
#include <cuda_runtime.h>

// (B, N, T, H) = (16, 256, 96, 128)
#define BB 16
#define NN 256
#define TT 96
#define HH 128
#define EPS 1e-5f
#define G  4            // (b,n) pairs per block in the main kernel

// Scratch (static __device__ — allocation-free)
__device__ float g_C[TT * HH];       // time_emb @ W3            (48 KB)
__device__ float g_nodeS[NN * HH];   // node_emb @ W2            (128 KB)
__device__ float g_Wf[TT * HH];      // Wp @ W1  (fused proj)    (48 KB)
__device__ float g_bias[HH];         // bp @ W1 + bf

// ---------------------------------------------------------------------------
// Prep kernel: all the tiny GEMMs. 449 blocks x 128 threads, one output row
// per block, one element per thread (128-FMA loop, coalesced over k).
//   r in [0,96)    : g_C[t=r]
//   r in [96,192)  : g_Wf[t=r-96]
//   r in [192,448) : g_nodeS[n=r-192]
//   r == 448       : g_bias
// ---------------------------------------------------------------------------
__global__ __launch_bounds__(HH) void prep_kernel(
    const float* __restrict__ Wp,
    const float* __restrict__ bp,
    const float* __restrict__ Wf,
    const float* __restrict__ bf,
    const float* __restrict__ node_emb,
    const float* __restrict__ time_emb) {

    const int r = blockIdx.x;
    const int k = threadIdx.x;
    const float* __restrict__ W1 = Wf;
    const float* __restrict__ W2 = Wf + HH * HH;
    const float* __restrict__ W3 = Wf + 2 * HH * HH;

    if (r < TT) {                       // C[t,k] = sum_h time_emb[t,h] W3[h,k]
        const int t = r;
        const float* __restrict__ v = time_emb + t * HH;
        float acc = 0.f;
#pragma unroll 8
        for (int h = 0; h < HH; h++) acc += v[h] * W3[h * HH + k];
        g_C[t * HH + k] = acc;
    } else if (r < 2 * TT) {            // Wf[t,k] = sum_h Wp[t,h] W1[h,k]
        const int t = r - TT;
        const float* __restrict__ v = Wp + t * HH;
        float acc = 0.f;
#pragma unroll 8
        for (int h = 0; h < HH; h++) acc += v[h] * W1[h * HH + k];
        g_Wf[t * HH + k] = acc;
    } else if (r < 2 * TT + NN) {       // nodeS[n,k] = sum_h node_emb[n,h] W2[h,k]
        const int n = r - 2 * TT;
        const float* __restrict__ v = node_emb + n * HH;
        float acc = 0.f;
#pragma unroll 8
        for (int h = 0; h < HH; h++) acc += v[h] * W2[h * HH + k];
        g_nodeS[n * HH + k] = acc;
    } else {                            // bias[k] = bf[k] + sum_h bp[h] W1[h,k]
        float acc = bf[k];
#pragma unroll 8
        for (int h = 0; h < HH; h++) acc += bp[h] * W1[h * HH + k];
        g_bias[k] = acc;
    }
}

// ---------------------------------------------------------------------------
// Main kernel: 1024 blocks x 256 threads; block handles G=4 (b,n) pairs.
// Phase 1: A[g,k] = bias[k] + nodeS[n,k] + sum_t xs[g,t] * Wfused[t,k]
// Phase 2: warp w owns t in [12w, 12w+12), processed as 3 quads of 4 rows.
//   Lane layout: grp = lane>>3 picks the row within a quad, il = lane&7.
//   Lane il owns interleaved columns {32j + 4il .. +4}, j=0..3, so every
//   STG.128 across the warp writes 4 rows x 128 contiguous bytes.
//   C slice (12 rows x 16 floats) lives in registers for the whole kernel.
//   Mean/var reduced with 3 shfl.xor rounds within 8-lane groups.
// ---------------------------------------------------------------------------
__global__ __launch_bounds__(256, 2) void gpe_main_kernel(
    const float* __restrict__ x,
    const float* __restrict__ gamma,
    const float* __restrict__ beta,
    float* __restrict__ out) {

    __shared__ float xs[G * TT];      // 1.5 KB
    __shared__ float As[G * HH];      // 2 KB
    __shared__ float gs[HH];
    __shared__ float bs[HH];

    const int bid  = blockIdx.x;      // pair group [bid*G, bid*G+G)
    const int tid  = threadIdx.x;
    const int pair0 = bid * G;

    // Stage x for the G pairs + gamma/beta
    for (int i = tid; i < G * TT; i += 256)
        xs[i] = x[(size_t)pair0 * TT + i];
    if (tid < HH) { gs[tid] = gamma[tid]; bs[tid] = beta[tid]; }
    __syncthreads();

    // Phase 1: A (512 outputs, 2 per thread), ~96 FMA each
    for (int i = tid; i < G * HH; i += 256) {
        const int g = i >> 7;
        const int k = i & (HH - 1);
        const int n = (pair0 + g) & (NN - 1);
        float acc = g_bias[k] + g_nodeS[n * HH + k];
        const float* __restrict__ xg = xs + g * TT;
#pragma unroll 8
        for (int t = 0; t < TT; t++)
            acc += xg[t] * g_Wf[t * HH + k];
        As[i] = acc;
    }
    __syncthreads();

    // Phase 2: streaming
    const int w   = tid >> 5;
    const int l   = tid & 31;
    const int grp = l >> 3;
    const int il  = l & 7;
    const int tb  = w * 12 + grp;     // this lane-group's base t (quads add 4q)

    // C slice in registers: c[q][j] = C[tb+4q][32j + 4il .. +4]
    float4 c[3][4];
#pragma unroll
    for (int q = 0; q < 3; q++) {
        const float* __restrict__ crow = g_C + (tb + 4 * q) * HH;
#pragma unroll
        for (int j = 0; j < 4; j++)
            c[q][j] = *reinterpret_cast<const float4*>(crow + 32 * j + 4 * il);
    }

    for (int g = 0; g < G; g++) {
        // A slice for this pair (same for all 4 lane-groups -> smem broadcast)
        float4 a[4];
#pragma unroll
        for (int j = 0; j < 4; j++)
            a[j] = *reinterpret_cast<const float4*>(As + g * HH + 32 * j + 4 * il);

        float* __restrict__ obase = out + ((size_t)(pair0 + g) * TT) * HH;

#pragma unroll
        for (int q = 0; q < 3; q++) {
            const int t = tb + 4 * q;

            float4 v[4];
            float s1 = 0.f, s2 = 0.f;
#pragma unroll
            for (int j = 0; j < 4; j++) {
                v[j].x = fmaxf(a[j].x + c[q][j].x, 0.f);
                v[j].y = fmaxf(a[j].y + c[q][j].y, 0.f);
                v[j].z = fmaxf(a[j].z + c[q][j].z, 0.f);
                v[j].w = fmaxf(a[j].w + c[q][j].w, 0.f);
                s1 += v[j].x + v[j].y + v[j].z + v[j].w;
                s2 += v[j].x * v[j].x + v[j].y * v[j].y
                    + v[j].z * v[j].z + v[j].w * v[j].w;
            }
            // 8-lane group reduction (offsets stay inside the group)
#pragma unroll
            for (int off = 1; off < 8; off <<= 1) {
                s1 += __shfl_xor_sync(0xffffffffu, s1, off);
                s2 += __shfl_xor_sync(0xffffffffu, s2, off);
            }
            const float mean = s1 * (1.f / HH);
            const float var  = s2 * (1.f / HH) - mean * mean;
            const float rstd = rsqrtf(var + EPS);

            float* __restrict__ orow = obase + t * HH;
#pragma unroll
            for (int j = 0; j < 4; j++) {
                const int col = 32 * j + 4 * il;
                const float4 gg = *reinterpret_cast<const float4*>(gs + col);
                const float4 bb = *reinterpret_cast<const float4*>(bs + col);
                float4 o;
                o.x = (v[j].x - mean) * rstd * gg.x + bb.x;
                o.y = (v[j].y - mean) * rstd * gg.y + bb.y;
                o.z = (v[j].z - mean) * rstd * gg.z + bb.z;
                o.w = (v[j].w - mean) * rstd * gg.w + bb.w;
                *reinterpret_cast<float4*>(orow + col) = o;
            }
        }
    }
}

// ---------------------------------------------------------------------------
// Inputs: 0:x 1:Wp 2:bp 3:Wf 4:bf 5:gamma 6:beta 7:node_emb 8:time_emb
// ---------------------------------------------------------------------------
extern "C" void kernel_launch(void* const* d_in, const int* in_sizes, int n_in,
                              void* d_out, int out_size) {
    const float* x        = (const float*)d_in[0];
    const float* Wp       = (const float*)d_in[1];
    const float* bp       = (const float*)d_in[2];
    const float* Wf       = (const float*)d_in[3];
    const float* bf       = (const float*)d_in[4];
    const float* gamma    = (const float*)d_in[5];
    const float* beta     = (const float*)d_in[6];
    const float* node_emb = (const float*)d_in[7];
    const float* time_emb = (const float*)d_in[8];
    float* out = (float*)d_out;

    prep_kernel<<<2 * TT + NN + 1, HH>>>(Wp, bp, Wf, bf, node_emb, time_emb);
    gpe_main_kernel<<<(BB * NN) / G, 256>>>(x, gamma, beta, out);
}

// round 3
// speedup vs baseline: 1.9381x; 1.2952x over previous
#include <cuda_runtime.h>

// (B, N, T, H) = (16, 256, 96, 128)
#define BB 16
#define NN 256
#define TT 96
#define HH 128
#define EPS 1e-5f
#define G  4            // (b,n) pairs per block in the main kernel

// Scratch (static __device__ — allocation-free)
__device__ float g_C[TT * HH];       // time_emb @ W3            (48 KB)
__device__ float g_nodeS[NN * HH];   // node_emb @ W2            (128 KB)
__device__ float g_Wf[TT * HH];      // Wp @ W1  (fused proj)    (48 KB)
__device__ float g_bias[HH];         // bp @ W1 + bf

// ---------------------------------------------------------------------------
// Prep kernel: all the tiny GEMMs. 449 blocks x 512 threads.
// 4-way split over the h reduction (part = tid>>7, 32 FMAs each) -> 4x MLP,
// 1/4 dependent-chain length vs one-thread-per-output. smem tree reduce.
//   r in [0,96)    : g_C[t=r]       = time_emb[r]   @ W3
//   r in [96,192)  : g_Wf[t=r-96]   = Wp[r-96]      @ W1
//   r in [192,448) : g_nodeS[r-192] = node_emb[..]  @ W2
//   r == 448       : g_bias         = bp @ W1 + bf
// ---------------------------------------------------------------------------
__global__ __launch_bounds__(512) void prep_kernel(
    const float* __restrict__ Wp,
    const float* __restrict__ bp,
    const float* __restrict__ Wf,
    const float* __restrict__ bf,
    const float* __restrict__ node_emb,
    const float* __restrict__ time_emb) {

    __shared__ float vsh[HH];
    __shared__ float partial[4][HH];

    const int r = blockIdx.x;
    const int k = threadIdx.x & (HH - 1);
    const int p = threadIdx.x >> 7;       // 0..3

    const float* __restrict__ v;
    const float* __restrict__ W;
    if (r < TT)                { v = time_emb + r * HH;        W = Wf + 2 * HH * HH; }
    else if (r < 2 * TT)       { v = Wp + (r - TT) * HH;       W = Wf; }
    else if (r < 2 * TT + NN)  { v = node_emb + (r - 2*TT)*HH; W = Wf + HH * HH; }
    else                       { v = bp;                       W = Wf; }

    if (threadIdx.x < HH) vsh[threadIdx.x] = v[threadIdx.x];
    __syncthreads();

    float acc = 0.f;
    const int h0 = p * 32;
#pragma unroll
    for (int hh = 0; hh < 32; hh++) {
        const int h = h0 + hh;
        acc += vsh[h] * W[h * HH + k];   // coalesced over k
    }
    partial[p][k] = acc;
    __syncthreads();

    if (threadIdx.x < HH) {
        float s = partial[0][k] + partial[1][k] + partial[2][k] + partial[3][k];
        if (r < TT)               g_C[r * HH + k] = s;
        else if (r < 2 * TT)      g_Wf[(r - TT) * HH + k] = s;
        else if (r < 2 * TT + NN) g_nodeS[(r - 2 * TT) * HH + k] = s;
        else                      g_bias[k] = s + bf[k];
    }
}

// ---------------------------------------------------------------------------
// Main kernel: 1024 blocks x 256 threads; block handles G=4 (b,n) pairs.
// Phase 1: A[g,k] = bias[k] + nodeS[n,k] + sum_t xs[g,t] * Wfused[t,k]
// Phase 2: warp w owns t in [12w,12w+12) as 3 quads of 4 rows. Lane layout:
//   grp = lane>>3 picks the row within a quad, il = lane&7 owns interleaved
//   columns {32j + 4il}, j=0..3 -> every STG.128 across the warp is 4 rows x
//   128 contiguous bytes. Quad loop OUTER (C slice loaded once, transient),
//   pair loop INNER (C reused 4x). 8-lane shfl reduction (3 rounds).
// ---------------------------------------------------------------------------
__global__ __launch_bounds__(256, 4) void gpe_main_kernel(
    const float* __restrict__ x,
    const float* __restrict__ gamma,
    const float* __restrict__ beta,
    float* __restrict__ out) {

    __shared__ float xs[G * TT];
    __shared__ float As[G * HH];
    __shared__ float gs[HH];
    __shared__ float bs[HH];

    const int tid   = threadIdx.x;
    const int pair0 = blockIdx.x * G;

    for (int i = tid; i < G * TT; i += 256)
        xs[i] = x[(size_t)pair0 * TT + i];
    if (tid < HH) { gs[tid] = gamma[tid]; bs[tid] = beta[tid]; }
    __syncthreads();

    // Phase 1: 512 outputs, 2 per thread, 96 FMA each
    for (int i = tid; i < G * HH; i += 256) {
        const int g = i >> 7;
        const int k = i & (HH - 1);
        const int n = (pair0 + g) & (NN - 1);
        float acc = __ldg(g_bias + k) + __ldg(g_nodeS + n * HH + k);
        const float* __restrict__ xg = xs + g * TT;
#pragma unroll 8
        for (int t = 0; t < TT; t++)
            acc += xg[t] * g_Wf[t * HH + k];
        As[i] = acc;
    }
    __syncthreads();

    // Phase 2
    const int w   = tid >> 5;
    const int l   = tid & 31;
    const int grp = l >> 3;
    const int il  = l & 7;
    const int tb  = w * 12 + grp;

#pragma unroll
    for (int q = 0; q < 3; q++) {
        const int t = tb + 4 * q;

        // C slice for this quad (transient registers, reused for G pairs)
        float4 c[4];
        const float* __restrict__ crow = g_C + t * HH;
#pragma unroll
        for (int j = 0; j < 4; j++)
            c[j] = __ldg(reinterpret_cast<const float4*>(crow + 32 * j + 4 * il));

        for (int g = 0; g < G; g++) {
            float4 v[4];
            float s1 = 0.f, s2 = 0.f;
#pragma unroll
            for (int j = 0; j < 4; j++) {
                const float4 a = *reinterpret_cast<const float4*>(
                    As + g * HH + 32 * j + 4 * il);
                v[j].x = fmaxf(a.x + c[j].x, 0.f);
                v[j].y = fmaxf(a.y + c[j].y, 0.f);
                v[j].z = fmaxf(a.z + c[j].z, 0.f);
                v[j].w = fmaxf(a.w + c[j].w, 0.f);
                s1 += v[j].x + v[j].y + v[j].z + v[j].w;
                s2 += v[j].x * v[j].x + v[j].y * v[j].y
                    + v[j].z * v[j].z + v[j].w * v[j].w;
            }
#pragma unroll
            for (int off = 1; off < 8; off <<= 1) {
                s1 += __shfl_xor_sync(0xffffffffu, s1, off);
                s2 += __shfl_xor_sync(0xffffffffu, s2, off);
            }
            const float mean = s1 * (1.f / HH);
            const float var  = s2 * (1.f / HH) - mean * mean;
            const float rstd = rsqrtf(var + EPS);

            float* __restrict__ orow =
                out + ((size_t)(pair0 + g) * TT + t) * HH;
#pragma unroll
            for (int j = 0; j < 4; j++) {
                const int col = 32 * j + 4 * il;
                const float4 gg = *reinterpret_cast<const float4*>(gs + col);
                const float4 bb = *reinterpret_cast<const float4*>(bs + col);
                float4 o;
                o.x = (v[j].x - mean) * rstd * gg.x + bb.x;
                o.y = (v[j].y - mean) * rstd * gg.y + bb.y;
                o.z = (v[j].z - mean) * rstd * gg.z + bb.z;
                o.w = (v[j].w - mean) * rstd * gg.w + bb.w;
                __stcs(reinterpret_cast<float4*>(orow + col), o);
            }
        }
    }
}

// ---------------------------------------------------------------------------
// Inputs: 0:x 1:Wp 2:bp 3:Wf 4:bf 5:gamma 6:beta 7:node_emb 8:time_emb
// ---------------------------------------------------------------------------
extern "C" void kernel_launch(void* const* d_in, const int* in_sizes, int n_in,
                              void* d_out, int out_size) {
    const float* x        = (const float*)d_in[0];
    const float* Wp       = (const float*)d_in[1];
    const float* bp       = (const float*)d_in[2];
    const float* Wf       = (const float*)d_in[3];
    const float* bf       = (const float*)d_in[4];
    const float* gamma    = (const float*)d_in[5];
    const float* beta     = (const float*)d_in[6];
    const float* node_emb = (const float*)d_in[7];
    const float* time_emb = (const float*)d_in[8];
    float* out = (float*)d_out;

    prep_kernel<<<2 * TT + NN + 1, 512>>>(Wp, bp, Wf, bf, node_emb, time_emb);
    gpe_main_kernel<<<(BB * NN) / G, 256>>>(x, gamma, beta, out);
}